// round 12
// baseline (speedup 1.0000x reference)
#include <cuda_runtime.h>
#include <cuda_fp16.h>
#include <math.h>
#include <stdint.h>

#define N_ELEC 8192
#define N_NUC  512
#define EMB    256
#define KER    256
#define DF     64
#define MID    128

// ---------------- scratch (device globals; no allocations allowed) ----------
__device__ __align__(16) float  g_HX[N_ELEC * KER];
__device__ __align__(16) float  g_Z[N_ELEC * 3 * KER];
__device__ __align__(16) __half g_Zh[N_ELEC * 3 * KER];
__device__ __align__(16) __half g_elech[N_ELEC * EMB];
// edge-kernel weight images in per-lane FRAGMENT order
__device__ __align__(16) __half g_w1Th[3][128 * 64];
__device__ __align__(16) __half g_w2Th[3][256 * 128];
// gemm_h images (n-major rows, perm16'd cols)
__device__ __align__(16) __half g_hwh[256 * 264];
__device__ __align__(16) __half g_GTh[256 * 776];

__device__ __host__ __forceinline__ int perm16(int n) {
    int c = (n >> 1) & 3, e = n & 1, ntp = (n >> 3) & 1;
    return (n & ~15) | (c << 2) | (ntp << 1) | e;
}

// ---------------- helpers ---------------------------------------------------
__device__ __forceinline__ void ldm_x4(uint32_t r[4], uint32_t saddr) {
    asm volatile("ldmatrix.sync.aligned.m8n8.x4.shared.b16 {%0,%1,%2,%3}, [%4];"
                 : "=r"(r[0]), "=r"(r[1]), "=r"(r[2]), "=r"(r[3]) : "r"(saddr));
}
__device__ __forceinline__ uint4 lds128(uint32_t saddr) {
    uint4 v;
    asm volatile("ld.shared.v4.b32 {%0,%1,%2,%3}, [%4];"
                 : "=r"(v.x), "=r"(v.y), "=r"(v.z), "=r"(v.w) : "r"(saddr));
    return v;
}
__device__ __forceinline__ void mma_f16(float acc[4], const uint32_t a[4],
                                        uint32_t b0, uint32_t b1) {
    asm volatile(
        "mma.sync.aligned.m16n8k16.row.col.f32.f16.f16.f32 "
        "{%0,%1,%2,%3}, {%4,%5,%6,%7}, {%8,%9}, {%0,%1,%2,%3};"
        : "+f"(acc[0]), "+f"(acc[1]), "+f"(acc[2]), "+f"(acc[3])
        : "r"(a[0]), "r"(a[1]), "r"(a[2]), "r"(a[3]), "r"(b0), "r"(b1));
}
__device__ __forceinline__ void red4(float* p, float x, float y, float z, float w) {
    asm volatile("red.global.add.v4.f32 [%0], {%1, %2, %3, %4};"
                 :: "l"(p), "f"(x), "f"(y), "f"(z), "f"(w) : "memory");
}
__device__ __forceinline__ void cp16(uint32_t saddr, const void* g) {
    asm volatile("cp.async.cg.shared.global [%0], [%1], 16;" :: "r"(saddr), "l"(g));
}
#define CP_COMMIT() asm volatile("cp.async.commit_group;" ::: "memory")
#define CP_WAIT(n)  asm volatile("cp.async.wait_group %0;" :: "n"(n) : "memory")

__device__ __forceinline__ uint32_t smem_u32(const void* p) {
    uint32_t a;
    asm("{ .reg .u64 t; cvta.to.shared.u64 t, %1; cvt.u32.u64 %0, t; }" : "=r"(a) : "l"(p));
    return a;
}
__device__ __forceinline__ uint32_t packh2(float x, float y) {   // lo=x, hi=y
    uint32_t r;
    asm("cvt.rn.f16x2.f32 %0, %1, %2;" : "=r"(r) : "f"(y), "f"(x));
    return r;
}
// fast shifted softplus via MUFU (validated R11)
__device__ __forceinline__ float sspf(float x) {
    float e;
    asm("ex2.approx.f32 %0, %1;" : "=f"(e) : "f"(x * 1.4426950408889634f));
    float l;
    asm("lg2.approx.f32 %0, %1;" : "=f"(l) : "f"(fmaf(e, 0.5f, 0.5f)));
    return l * 0.69314718055994531f;
}

// ================= elementwise fp32 -> fp16 =================================
__global__ void f2h(const float4* __restrict__ src, uint2* __restrict__ dst, int n4) {
    int i = blockIdx.x * blockDim.x + threadIdx.x;
    if (i < n4) {
        float4 v = src[i];
        uint2 h;
        h.x = packh2(v.x, v.y);
        h.y = packh2(v.z, v.w);
        dst[i] = h;
    }
}

// ================= weight prep (parallel over grid.y slices) ================
__global__ void prep_weights(const float* __restrict__ w1_0, const float* __restrict__ w1_1,
                             const float* __restrict__ w1_2,
                             const float* __restrict__ w2_0, const float* __restrict__ w2_1,
                             const float* __restrict__ w2_2,
                             const float* __restrict__ g_0, const float* __restrict__ g_1,
                             const float* __restrict__ g_2,
                             const float* __restrict__ h_w)
{
    int ty = blockIdx.x;
    const float* w1 = (ty == 0) ? w1_0 : (ty == 1) ? w1_1 : w1_2;
    const float* w2 = (ty == 0) ? w2_0 : (ty == 1) ? w2_1 : w2_2;
    const float* gg = (ty == 0) ? g_0  : (ty == 1) ? g_1  : g_2;
    const int t0 = threadIdx.x + blockIdx.y * blockDim.x;
    const int stp = blockDim.x * gridDim.y;
    for (int i = t0; i < 128 * 64; i += stp) {
        int h = i & 7, lane = (i >> 3) & 31, ks = (i >> 8) & 3, nblk = i >> 10;
        int gl = lane >> 2, cl = lane & 3, reg = h >> 1, e = h & 1;
        int k = ks * 16 + (reg & 1) * 8 + 2 * cl + e;
        int n = nblk * 16 + (reg >> 1) * 8 + gl;
        g_w1Th[ty][i] = __float2half(w1[k * 128 + n]);
    }
    for (int i = t0; i < 256 * 128; i += stp) {
        int h = i & 7, lane = (i >> 3) & 31, ks = (i >> 8) & 7, nblk = i >> 11;
        int gl = lane >> 2, cl = lane & 3, reg = h >> 1, e = h & 1;
        int k = ks * 16 + (reg & 1) * 8 + 2 * cl + e;
        int n = nblk * 16 + perm16((reg >> 1) * 8 + gl);
        g_w2Th[ty][i] = __float2half(w2[k * 256 + n]);
    }
    for (int i = t0; i < 256 * 256; i += stp) {
        int n = i >> 8, kk = i & 255;
        g_GTh[n * 776 + ty * 256 + kk] = __float2half(gg[kk * 256 + perm16(n)]);
    }
    if (ty == 0)
        for (int i = t0; i < 256 * 256; i += stp) {
            int n = i >> 8, k = i & 255;
            g_hwh[n * 264 + k] = __float2half(h_w[k * 256 + perm16(n)]);
        }
}

// ================= fp16 tensor-core GEMM (unchanged) ========================
#define GSM_A0 0
#define GSM_A1 9216
#define GSM_B0 18432
#define GSM_B1 36864
#define GSM_TOT 55296

__global__ void __launch_bounds__(256, 3)
gemm_h(const __half* __restrict__ A, int K,
       const __half* __restrict__ B, int Kpad,
       const float* __restrict__ Cin, float* __restrict__ Out)
{
    extern __shared__ char smem[];
    const uint32_t sbase = smem_u32(smem);
    const int t = threadIdx.x, warp = t >> 5, lane = t & 31;
    const int wm = warp & 3, wn = warp >> 2;
    const int g = lane >> 2, c = lane & 3;
    const int n0 = blockIdx.x * 128, m0 = blockIdx.y * 64;
    const int nch = K / 64;

    const int lrowA = (lane & 7) + ((lane >> 3) & 1) * 8;
    const int lkA   = (lane >> 4) * 8;
    const int lrowB = ((lane >> 4) << 3) + (lane & 7);
    const int lkB   = ((lane >> 3) & 1) * 8;

    float acc[8][4];
#pragma unroll
    for (int j = 0; j < 8; j++)
#pragma unroll
        for (int p = 0; p < 4; p++) acc[j][p] = 0.f;

#define LOAD_CHUNK(ch) do {                                                     \
        uint32_t abuf = sbase + (((ch) & 1) ? GSM_A1 : GSM_A0);                 \
        uint32_t bbuf = sbase + (((ch) & 1) ? GSM_B1 : GSM_B0);                 \
        const char* ag = (const char*)(A + (long)m0 * K + (ch) * 64);           \
        _Pragma("unroll")                                                       \
        for (int i = 0; i < 2; i++) {                                           \
            int idx = t + 256 * i, row = idx >> 3, cc = idx & 7;                \
            cp16(abuf + row * 144 + cc * 16, ag + (long)row * K * 2 + cc * 16); \
        }                                                                       \
        const char* bg = (const char*)(B + (long)n0 * Kpad + (ch) * 64);        \
        _Pragma("unroll")                                                       \
        for (int i = 0; i < 4; i++) {                                           \
            int idx = t + 256 * i, row = idx >> 3, cc = idx & 7;                \
            cp16(bbuf + row * 144 + cc * 16, bg + (long)row * Kpad * 2 + cc * 16); \
        }                                                                       \
        CP_COMMIT();                                                            \
    } while (0)

    LOAD_CHUNK(0);
    for (int ch = 0; ch < nch; ch++) {
        if (ch + 1 < nch) { LOAD_CHUNK(ch + 1); CP_WAIT(1); }
        else              { CP_WAIT(0); }
        __syncthreads();
        uint32_t abuf = sbase + ((ch & 1) ? GSM_A1 : GSM_A0);
        uint32_t bbuf = sbase + ((ch & 1) ? GSM_B1 : GSM_B0);
        uint32_t aB = abuf + (wm * 16 + lrowA) * 144 + lkA * 2;
        uint32_t bB = bbuf + (wn * 64 + lrowB) * 144 + lkB * 2;
#pragma unroll
        for (int s = 0; s < 4; s++) {
            uint32_t a[4];
            ldm_x4(a, aB + s * 32);
#pragma unroll
            for (int p = 0; p < 4; p++) {
                uint32_t b[4];
                ldm_x4(b, bB + p * 16 * 144 + s * 32);
                mma_f16(acc[2 * p],     a, b[0], b[1]);
                mma_f16(acc[2 * p + 1], a, b[2], b[3]);
            }
        }
        __syncthreads();
    }

    int ra = m0 + wm * 16 + g, rb = ra + 8;
#pragma unroll
    for (int p = 0; p < 4; p++) {
        int col = n0 + wn * 64 + p * 16 + 4 * c;
        float4 v0 = make_float4(acc[2*p][0], acc[2*p][1], acc[2*p+1][0], acc[2*p+1][1]);
        float4 v1 = make_float4(acc[2*p][2], acc[2*p][3], acc[2*p+1][2], acc[2*p+1][3]);
        if (Cin) {
            float4 c0 = *(const float4*)(Cin + (long)ra * 256 + col);
            float4 c1 = *(const float4*)(Cin + (long)rb * 256 + col);
            v0.x += c0.x; v0.y += c0.y; v0.z += c0.z; v0.w += c0.w;
            v1.x += c1.x; v1.y += c1.y; v1.z += c1.z; v1.w += c1.w;
        }
        *(float4*)(Out + (long)ra * 256 + col) = v0;
        *(float4*)(Out + (long)rb * 256 + col) = v1;
    }
}

// ================= fused fp16 mma edge kernel (256 edges/CTA) ===============
// Each warp owns 32 edge-rows (two 16-row m-tiles) -> stage-2 B fragment loads
// serve 4 MMAs each (was 2): per-edge B smem traffic halved.
// smem bytes:
//   0: b1[128] (512)   512: send[256] (1024)   1536: recv[256] (1024)
//   2560:  dist half [256][144B]  (36864) -> 39424
//   39424: w1 fragment image (16384) -> 55808
//   55808: w2 quarter buf A (16384) -> 72192
//   72192: w2 quarter buf B (16384) -> 88576
#define SH_B1    0
#define SH_SEND  512
#define SH_RECV  1536
#define SH_DIST  2560
#define SH_W1T   39424
#define SH_W2A   55808
#define SH_W2B   72192
#define SMEM_EDGE 88576

__global__ void __launch_bounds__(256, 2)
edge_fused(const float* __restrict__ dist0, const float* __restrict__ dist1,
           const float* __restrict__ dist2,
           const float* __restrict__ b1_0, const float* __restrict__ b1_1,
           const float* __restrict__ b1_2,
           const float* __restrict__ HX, const float* __restrict__ nuc,
           const int* __restrict__ s0, const int* __restrict__ s1, const int* __restrict__ s2,
           const int* __restrict__ r0p, const int* __restrict__ r1p, const int* __restrict__ r2p,
           float* __restrict__ Z, int nblk)
{
    extern __shared__ char smem[];
    float* smF = (float*)smem;
    const uint32_t sbase = smem_u32(smem);
    const int t = threadIdx.x, warp = t >> 5, lane = t & 31;
    const int g = lane >> 2, c = lane & 3;
    const int wrow = warp * 32;

    const int ty  = blockIdx.x / nblk;
    const int blk = blockIdx.x - ty * nblk;
    const float* dist  = (ty == 0) ? dist0 : (ty == 1) ? dist1 : dist2;
    const float* b1    = (ty == 0) ? b1_0  : (ty == 1) ? b1_1  : b1_2;
    const int*   snd   = (ty == 0) ? s0 : (ty == 1) ? s1 : s2;
    const int*   rcv   = (ty == 0) ? r0p : (ty == 1) ? r1p : r2p;
    const float* hxsrc = (ty == 2) ? nuc : HX;
    const int    zoff  = ty * KER;
    const long   e0    = (long)blk * 256;
    const __half* w1T  = g_w1Th[ty];
    const __half* w2T  = g_w2Th[ty];

    // ---- fill ----
    if (t < 128) smF[(SH_B1 >> 2) + t] = b1[t];
    ((int*)smem)[(SH_SEND >> 2) + t] = snd[e0 + t];
    ((int*)smem)[(SH_RECV >> 2) + t] = rcv[e0 + t];
    {
        const float4* dr = (const float4*)(dist + (e0 + t) * DF);
        char* dst = smem + SH_DIST + t * 144;
#pragma unroll
        for (int j = 0; j < 16; j++) {
            float4 v = dr[j];
            uint2 h;
            h.x = packh2(v.x, v.y);
            h.y = packh2(v.z, v.w);
            *(uint2*)(dst + j * 8) = h;
        }
    }
#pragma unroll
    for (int i = 0; i < 4; i++)
        cp16(sbase + SH_W1T + (t + 256 * i) * 16, (const char*)w1T + (t + 256 * i) * 16);
    CP_COMMIT();
#pragma unroll
    for (int i = 0; i < 4; i++)
        cp16(sbase + SH_W2A + (t + 256 * i) * 16, (const char*)w2T + (t + 256 * i) * 16);
    CP_COMMIT();

    CP_WAIT(1);
    __syncthreads();

    const int lrowA = (lane & 7) + ((lane >> 3) & 1) * 8;
    const int lkA   = (lane >> 4) * 8;
    const uint32_t w1s = sbase + SH_W1T + lane * 16;

    // ---- stage 1 (per m-tile): mid fragments into mreg[mt] ----
    uint32_t mreg[2][8][4];
#pragma unroll
    for (int mt = 0; mt < 2; mt++) {
        const uint32_t aBase = sbase + SH_DIST + (wrow + mt * 16 + lrowA) * 144 + lkA * 2;
#pragma unroll
        for (int pass = 0; pass < 2; pass++) {
            float acc[8][4];
#pragma unroll
            for (int j = 0; j < 8; j++)
#pragma unroll
                for (int q = 0; q < 4; q++) acc[j][q] = 0.f;
#pragma unroll
            for (int s = 0; s < 4; s++) {
                uint32_t a[4];
                ldm_x4(a, aBase + s * 32);
#pragma unroll
                for (int p = 0; p < 4; p++) {
                    uint4 b = lds128(w1s + ((pass * 4 + p) * 4 + s) * 512);
                    mma_f16(acc[2 * p],     a, b.x, b.y);
                    mma_f16(acc[2 * p + 1], a, b.z, b.w);
                }
            }
            const float* sB1 = smF + (SH_B1 >> 2);
#pragma unroll
            for (int p = 0; p < 4; p++) {
                int nt0 = pass * 8 + 2 * p, nt1 = nt0 + 1;
                float bA0 = sB1[nt0 * 8 + 2 * c], bA1 = sB1[nt0 * 8 + 2 * c + 1];
                float bB0 = sB1[nt1 * 8 + 2 * c], bB1 = sB1[nt1 * 8 + 2 * c + 1];
                int s2i = pass * 4 + p;
                mreg[mt][s2i][0] = packh2(sspf(acc[2*p][0] + bA0),   sspf(acc[2*p][1] + bA1));
                mreg[mt][s2i][1] = packh2(sspf(acc[2*p][2] + bA0),   sspf(acc[2*p][3] + bA1));
                mreg[mt][s2i][2] = packh2(sspf(acc[2*p+1][0] + bB0), sspf(acc[2*p+1][1] + bB1));
                mreg[mt][s2i][3] = packh2(sspf(acc[2*p+1][2] + bB0), sspf(acc[2*p+1][3] + bB1));
            }
        }
    }

    // ---- epilogue pointers for 4 edges/thread (2 m-tiles x 2 halves) ----
    const float* hx[4];
    float* Zp[4];
#pragma unroll
    for (int i = 0; i < 4; i++) {
        int row = wrow + (i >> 1) * 16 + g + (i & 1) * 8;
        hx[i] = hxsrc + (long)((int*)smem)[(SH_SEND >> 2) + row] * KER;
        Zp[i] = Z + (long)((int*)smem)[(SH_RECV >> 2) + row] * (3 * KER) + zoff;
    }

    CP_WAIT(0);
    __syncthreads();

    // ---- stage 2: B fragment shared across both m-tiles ----
#pragma unroll
    for (int q = 0; q < 4; q++) {
        if (q < 3) {
            uint32_t dstq = sbase + (((q + 1) & 1) ? SH_W2B : SH_W2A);
            const char* srcq = (const char*)(w2T + (long)(q + 1) * 64 * 128);
#pragma unroll
            for (int i = 0; i < 4; i++)
                cp16(dstq + (t + 256 * i) * 16, srcq + (t + 256 * i) * 16);
            CP_COMMIT();
        }
        const uint32_t swq = sbase + ((q & 1) ? SH_W2B : SH_W2A) + lane * 16;
#pragma unroll
        for (int nb = 0; nb < 4; nb++) {
            float acc2[2][2][4];
#pragma unroll
            for (int mt = 0; mt < 2; mt++)
#pragma unroll
                for (int j = 0; j < 2; j++)
#pragma unroll
                    for (int p = 0; p < 4; p++) acc2[mt][j][p] = 0.f;
#pragma unroll
            for (int s = 0; s < 8; s++) {
                uint4 b = lds128(swq + (nb * 8 + s) * 512);
                mma_f16(acc2[0][0], mreg[0][s], b.x, b.y);
                mma_f16(acc2[0][1], mreg[0][s], b.z, b.w);
                mma_f16(acc2[1][0], mreg[1][s], b.x, b.y);
                mma_f16(acc2[1][1], mreg[1][s], b.z, b.w);
            }
            int base = q * 64 + nb * 16 + 4 * c;
#pragma unroll
            for (int mt = 0; mt < 2; mt++) {
                float4 h0 = *(const float4*)(hx[2 * mt] + base);
                red4(Zp[2 * mt] + base,
                     acc2[mt][0][0] * h0.x, acc2[mt][0][1] * h0.y,
                     acc2[mt][1][0] * h0.z, acc2[mt][1][1] * h0.w);
                float4 h1 = *(const float4*)(hx[2 * mt + 1] + base);
                red4(Zp[2 * mt + 1] + base,
                     acc2[mt][0][2] * h1.x, acc2[mt][0][3] * h1.y,
                     acc2[mt][1][2] * h1.z, acc2[mt][1][3] * h1.w);
            }
        }
        CP_WAIT(0);
        __syncthreads();
    }
}

// ---------------- launcher --------------------------------------------------
extern "C" void kernel_launch(void* const* d_in, const int* in_sizes, int n_in,
                              void* d_out, int out_size)
{
    const float* elec = (const float*)d_in[0];
    const float* nuc  = (const float*)d_in[1];
    const float *dist[3], *w1[3], *b1[3], *w2[3], *g[3];

    bool dictOrder = (in_sizes[3] == DF * MID);
    if (dictOrder) {
        const int base[3] = {2, 7, 12};
        for (int tI = 0; tI < 3; tI++) {
            dist[tI] = (const float*)d_in[base[tI] + 0];
            w1[tI]   = (const float*)d_in[base[tI] + 1];
            b1[tI]   = (const float*)d_in[base[tI] + 2];
            w2[tI]   = (const float*)d_in[base[tI] + 3];
            g[tI]    = (const float*)d_in[base[tI] + 4];
        }
    } else {
        for (int tI = 0; tI < 3; tI++) {
            dist[tI] = (const float*)d_in[2 + tI];
            w1[tI]   = (const float*)d_in[5 + 3 * tI];
            b1[tI]   = (const float*)d_in[6 + 3 * tI];
            w2[tI]   = (const float*)d_in[7 + 3 * tI];
            g[tI]    = (const float*)d_in[14 + tI];
        }
    }
    const float* h_w     = (const float*)d_in[17];
    const int*   send[3] = {(const int*)d_in[18], (const int*)d_in[19], (const int*)d_in[20]};
    const int*   recv[3] = {(const int*)d_in[21], (const int*)d_in[22], (const int*)d_in[23]};
    const int    E = in_sizes[2] / DF;
    const int    nblk = E / 256;

    float *HX, *Z;
    __half *Zh, *ELh, *HWh, *GTh;
    cudaGetSymbolAddress((void**)&HX,  g_HX);
    cudaGetSymbolAddress((void**)&Z,   g_Z);
    cudaGetSymbolAddress((void**)&Zh,  g_Zh);
    cudaGetSymbolAddress((void**)&ELh, g_elech);
    cudaGetSymbolAddress((void**)&HWh, g_hwh);
    cudaGetSymbolAddress((void**)&GTh, g_GTh);

    cudaFuncSetAttribute(edge_fused, cudaFuncAttributeMaxDynamicSharedMemorySize, SMEM_EDGE);
    cudaFuncSetAttribute(gemm_h, cudaFuncAttributeMaxDynamicSharedMemorySize, GSM_TOT);

    cudaMemsetAsync(Z, 0, sizeof(float) * N_ELEC * 3 * KER);

    prep_weights<<<dim3(3, 16), 256>>>(w1[0], w1[1], w1[2], w2[0], w2[1], w2[2],
                                       g[0], g[1], g[2], h_w);

    // electrons -> fp16
    {
        int n4 = N_ELEC * EMB / 4;
        f2h<<<(n4 + 255) / 256, 256>>>((const float4*)elec, (uint2*)ELh, n4);
    }
    // HX = elec @ h_w  (fp16 mma)
    {
        dim3 grid(2, N_ELEC / 64);
        gemm_h<<<grid, 256, GSM_TOT>>>(ELh, EMB, HWh, 264, nullptr, HX);
    }
    // fused fp16-mma edge kernel, 256 edges/CTA, all 3 types
    edge_fused<<<3 * nblk, 256, SMEM_EDGE>>>(dist[0], dist[1], dist[2],
                                             b1[0], b1[1], b1[2],
                                             HX, nuc,
                                             send[0], send[1], send[2],
                                             recv[0], recv[1], recv[2],
                                             Z, nblk);
    // Z -> fp16
    {
        int n4 = N_ELEC * 3 * KER / 4;
        f2h<<<(n4 + 255) / 256, 256>>>((const float4*)Z, (uint2*)Zh, n4);
    }
    // out = elec + Z @ Gcat  (fp16 mma)
    {
        dim3 grid(2, N_ELEC / 64);
        gemm_h<<<grid, 256, GSM_TOT>>>(Zh, 3 * KER, GTh, 776, elec, (float*)d_out);
    }
}

// round 13
// speedup vs baseline: 1.0079x; 1.0079x over previous
#include <cuda_runtime.h>
#include <cuda_fp16.h>
#include <math.h>
#include <stdint.h>

#define N_ELEC 8192
#define N_NUC  512
#define EMB    256
#define KER    256
#define DF     64
#define MID    128

// ---------------- scratch (device globals; no allocations allowed) ----------
__device__ __align__(16) float  g_HX[N_ELEC * KER];
__device__ __align__(16) float  g_Z[N_ELEC * 3 * KER];
__device__ __align__(16) __half g_Zh[N_ELEC * 3 * KER];
__device__ __align__(16) __half g_elech[N_ELEC * EMB];
// edge-kernel weight images in per-lane FRAGMENT order
__device__ __align__(16) __half g_w1Th[3][128 * 64];
__device__ __align__(16) __half g_w2Th[3][256 * 128];
// gemm_h images (n-major rows, perm16'd cols)
__device__ __align__(16) __half g_hwh[256 * 264];
__device__ __align__(16) __half g_GTh[256 * 776];

__device__ __host__ __forceinline__ int perm16(int n) {
    int c = (n >> 1) & 3, e = n & 1, ntp = (n >> 3) & 1;
    return (n & ~15) | (c << 2) | (ntp << 1) | e;
}

// ---------------- helpers ---------------------------------------------------
__device__ __forceinline__ void ldm_x4(uint32_t r[4], uint32_t saddr) {
    asm volatile("ldmatrix.sync.aligned.m8n8.x4.shared.b16 {%0,%1,%2,%3}, [%4];"
                 : "=r"(r[0]), "=r"(r[1]), "=r"(r[2]), "=r"(r[3]) : "r"(saddr));
}
__device__ __forceinline__ uint4 lds128(uint32_t saddr) {
    uint4 v;
    asm volatile("ld.shared.v4.b32 {%0,%1,%2,%3}, [%4];"
                 : "=r"(v.x), "=r"(v.y), "=r"(v.z), "=r"(v.w) : "r"(saddr));
    return v;
}
__device__ __forceinline__ void mma_f16(float acc[4], const uint32_t a[4],
                                        uint32_t b0, uint32_t b1) {
    asm volatile(
        "mma.sync.aligned.m16n8k16.row.col.f32.f16.f16.f32 "
        "{%0,%1,%2,%3}, {%4,%5,%6,%7}, {%8,%9}, {%0,%1,%2,%3};"
        : "+f"(acc[0]), "+f"(acc[1]), "+f"(acc[2]), "+f"(acc[3])
        : "r"(a[0]), "r"(a[1]), "r"(a[2]), "r"(a[3]), "r"(b0), "r"(b1));
}
__device__ __forceinline__ void red4(float* p, float x, float y, float z, float w) {
    asm volatile("red.global.add.v4.f32 [%0], {%1, %2, %3, %4};"
                 :: "l"(p), "f"(x), "f"(y), "f"(z), "f"(w) : "memory");
}
__device__ __forceinline__ void cp16(uint32_t saddr, const void* g) {
    asm volatile("cp.async.cg.shared.global [%0], [%1], 16;" :: "r"(saddr), "l"(g));
}
#define CP_COMMIT() asm volatile("cp.async.commit_group;" ::: "memory")
#define CP_WAIT(n)  asm volatile("cp.async.wait_group %0;" :: "n"(n) : "memory")

__device__ __forceinline__ uint32_t smem_u32(const void* p) {
    uint32_t a;
    asm("{ .reg .u64 t; cvta.to.shared.u64 t, %1; cvt.u32.u64 %0, t; }" : "=r"(a) : "l"(p));
    return a;
}
__device__ __forceinline__ uint32_t packh2(float x, float y) {   // lo=x, hi=y
    uint32_t r;
    asm("cvt.rn.f16x2.f32 %0, %1, %2;" : "=r"(r) : "f"(y), "f"(x));
    return r;
}
// fast shifted softplus via MUFU (validated R11)
__device__ __forceinline__ float sspf(float x) {
    float e;
    asm("ex2.approx.f32 %0, %1;" : "=f"(e) : "f"(x * 1.4426950408889634f));
    float l;
    asm("lg2.approx.f32 %0, %1;" : "=f"(l) : "f"(fmaf(e, 0.5f, 0.5f)));
    return l * 0.69314718055994531f;
}

// ================= elementwise fp32 -> fp16 =================================
__global__ void f2h(const float4* __restrict__ src, uint2* __restrict__ dst, int n4) {
    int i = blockIdx.x * blockDim.x + threadIdx.x;
    if (i < n4) {
        float4 v = src[i];
        uint2 h;
        h.x = packh2(v.x, v.y);
        h.y = packh2(v.z, v.w);
        dst[i] = h;
    }
}

// ================= weight prep (parallel over grid.y slices) ================
__global__ void prep_weights(const float* __restrict__ w1_0, const float* __restrict__ w1_1,
                             const float* __restrict__ w1_2,
                             const float* __restrict__ w2_0, const float* __restrict__ w2_1,
                             const float* __restrict__ w2_2,
                             const float* __restrict__ g_0, const float* __restrict__ g_1,
                             const float* __restrict__ g_2,
                             const float* __restrict__ h_w)
{
    int ty = blockIdx.x;
    const float* w1 = (ty == 0) ? w1_0 : (ty == 1) ? w1_1 : w1_2;
    const float* w2 = (ty == 0) ? w2_0 : (ty == 1) ? w2_1 : w2_2;
    const float* gg = (ty == 0) ? g_0  : (ty == 1) ? g_1  : g_2;
    const int t0 = threadIdx.x + blockIdx.y * blockDim.x;
    const int stp = blockDim.x * gridDim.y;
    for (int i = t0; i < 128 * 64; i += stp) {
        int h = i & 7, lane = (i >> 3) & 31, ks = (i >> 8) & 3, nblk = i >> 10;
        int gl = lane >> 2, cl = lane & 3, reg = h >> 1, e = h & 1;
        int k = ks * 16 + (reg & 1) * 8 + 2 * cl + e;
        int n = nblk * 16 + (reg >> 1) * 8 + gl;
        g_w1Th[ty][i] = __float2half(w1[k * 128 + n]);
    }
    for (int i = t0; i < 256 * 128; i += stp) {
        int h = i & 7, lane = (i >> 3) & 31, ks = (i >> 8) & 7, nblk = i >> 11;
        int gl = lane >> 2, cl = lane & 3, reg = h >> 1, e = h & 1;
        int k = ks * 16 + (reg & 1) * 8 + 2 * cl + e;
        int n = nblk * 16 + perm16((reg >> 1) * 8 + gl);
        g_w2Th[ty][i] = __float2half(w2[k * 256 + n]);
    }
    for (int i = t0; i < 256 * 256; i += stp) {
        int n = i >> 8, kk = i & 255;
        g_GTh[n * 776 + ty * 256 + kk] = __float2half(gg[kk * 256 + perm16(n)]);
    }
    if (ty == 0)
        for (int i = t0; i < 256 * 256; i += stp) {
            int n = i >> 8, k = i & 255;
            g_hwh[n * 264 + k] = __float2half(h_w[k * 256 + perm16(n)]);
        }
}

// ================= fp16 tensor-core GEMM (unchanged) ========================
#define GSM_A0 0
#define GSM_A1 9216
#define GSM_B0 18432
#define GSM_B1 36864
#define GSM_TOT 55296

__global__ void __launch_bounds__(256, 3)
gemm_h(const __half* __restrict__ A, int K,
       const __half* __restrict__ B, int Kpad,
       const float* __restrict__ Cin, float* __restrict__ Out)
{
    extern __shared__ char smem[];
    const uint32_t sbase = smem_u32(smem);
    const int t = threadIdx.x, warp = t >> 5, lane = t & 31;
    const int wm = warp & 3, wn = warp >> 2;
    const int g = lane >> 2, c = lane & 3;
    const int n0 = blockIdx.x * 128, m0 = blockIdx.y * 64;
    const int nch = K / 64;

    const int lrowA = (lane & 7) + ((lane >> 3) & 1) * 8;
    const int lkA   = (lane >> 4) * 8;
    const int lrowB = ((lane >> 4) << 3) + (lane & 7);
    const int lkB   = ((lane >> 3) & 1) * 8;

    float acc[8][4];
#pragma unroll
    for (int j = 0; j < 8; j++)
#pragma unroll
        for (int p = 0; p < 4; p++) acc[j][p] = 0.f;

#define LOAD_CHUNK(ch) do {                                                     \
        uint32_t abuf = sbase + (((ch) & 1) ? GSM_A1 : GSM_A0);                 \
        uint32_t bbuf = sbase + (((ch) & 1) ? GSM_B1 : GSM_B0);                 \
        const char* ag = (const char*)(A + (long)m0 * K + (ch) * 64);           \
        _Pragma("unroll")                                                       \
        for (int i = 0; i < 2; i++) {                                           \
            int idx = t + 256 * i, row = idx >> 3, cc = idx & 7;                \
            cp16(abuf + row * 144 + cc * 16, ag + (long)row * K * 2 + cc * 16); \
        }                                                                       \
        const char* bg = (const char*)(B + (long)n0 * Kpad + (ch) * 64);        \
        _Pragma("unroll")                                                       \
        for (int i = 0; i < 4; i++) {                                           \
            int idx = t + 256 * i, row = idx >> 3, cc = idx & 7;                \
            cp16(bbuf + row * 144 + cc * 16, bg + (long)row * Kpad * 2 + cc * 16); \
        }                                                                       \
        CP_COMMIT();                                                            \
    } while (0)

    LOAD_CHUNK(0);
    for (int ch = 0; ch < nch; ch++) {
        if (ch + 1 < nch) { LOAD_CHUNK(ch + 1); CP_WAIT(1); }
        else              { CP_WAIT(0); }
        __syncthreads();
        uint32_t abuf = sbase + ((ch & 1) ? GSM_A1 : GSM_A0);
        uint32_t bbuf = sbase + ((ch & 1) ? GSM_B1 : GSM_B0);
        uint32_t aB = abuf + (wm * 16 + lrowA) * 144 + lkA * 2;
        uint32_t bB = bbuf + (wn * 64 + lrowB) * 144 + lkB * 2;
#pragma unroll
        for (int s = 0; s < 4; s++) {
            uint32_t a[4];
            ldm_x4(a, aB + s * 32);
#pragma unroll
            for (int p = 0; p < 4; p++) {
                uint32_t b[4];
                ldm_x4(b, bB + p * 16 * 144 + s * 32);
                mma_f16(acc[2 * p],     a, b[0], b[1]);
                mma_f16(acc[2 * p + 1], a, b[2], b[3]);
            }
        }
        __syncthreads();
    }

    int ra = m0 + wm * 16 + g, rb = ra + 8;
#pragma unroll
    for (int p = 0; p < 4; p++) {
        int col = n0 + wn * 64 + p * 16 + 4 * c;
        float4 v0 = make_float4(acc[2*p][0], acc[2*p][1], acc[2*p+1][0], acc[2*p+1][1]);
        float4 v1 = make_float4(acc[2*p][2], acc[2*p][3], acc[2*p+1][2], acc[2*p+1][3]);
        if (Cin) {
            float4 c0 = *(const float4*)(Cin + (long)ra * 256 + col);
            float4 c1 = *(const float4*)(Cin + (long)rb * 256 + col);
            v0.x += c0.x; v0.y += c0.y; v0.z += c0.z; v0.w += c0.w;
            v1.x += c1.x; v1.y += c1.y; v1.z += c1.z; v1.w += c1.w;
        }
        *(float4*)(Out + (long)ra * 256 + col) = v0;
        *(float4*)(Out + (long)rb * 256 + col) = v1;
    }
}

// ================= fused fp16 mma edge kernel (256 edges/CTA, lean regs) ====
// Same tiling as R12 (B fragment shared across two m-tiles per warp), but
// epilogue pointers replaced by 32-bit element offsets to avoid the register
// spill that killed R12 (regs hit 128 cap -> mreg spilled -> DRAM 24%).
#define SH_B1    0
#define SH_SEND  512
#define SH_RECV  1536
#define SH_DIST  2560
#define SH_W1T   39424
#define SH_W2A   55808
#define SH_W2B   72192
#define SMEM_EDGE 88576

__global__ void __launch_bounds__(256, 2)
edge_fused(const float* __restrict__ dist0, const float* __restrict__ dist1,
           const float* __restrict__ dist2,
           const float* __restrict__ b1_0, const float* __restrict__ b1_1,
           const float* __restrict__ b1_2,
           const float* __restrict__ HX, const float* __restrict__ nuc,
           const int* __restrict__ s0, const int* __restrict__ s1, const int* __restrict__ s2,
           const int* __restrict__ r0p, const int* __restrict__ r1p, const int* __restrict__ r2p,
           float* __restrict__ Z, int nblk)
{
    extern __shared__ char smem[];
    float* smF = (float*)smem;
    const uint32_t sbase = smem_u32(smem);
    const int t = threadIdx.x, warp = t >> 5, lane = t & 31;
    const int g = lane >> 2, c = lane & 3;
    const int wrow = warp * 32;

    const int ty  = blockIdx.x / nblk;
    const int blk = blockIdx.x - ty * nblk;
    const float* dist  = (ty == 0) ? dist0 : (ty == 1) ? dist1 : dist2;
    const float* b1    = (ty == 0) ? b1_0  : (ty == 1) ? b1_1  : b1_2;
    const int*   snd   = (ty == 0) ? s0 : (ty == 1) ? s1 : s2;
    const int*   rcv   = (ty == 0) ? r0p : (ty == 1) ? r1p : r2p;
    const float* hxsrc = (ty == 2) ? nuc : HX;
    const int    zoff  = ty * KER;
    const long   e0    = (long)blk * 256;
    const __half* w1T  = g_w1Th[ty];
    const __half* w2T  = g_w2Th[ty];

    // ---- fill ----
    if (t < 128) smF[(SH_B1 >> 2) + t] = b1[t];
    ((int*)smem)[(SH_SEND >> 2) + t] = snd[e0 + t];
    ((int*)smem)[(SH_RECV >> 2) + t] = rcv[e0 + t];
    {
        const float4* dr = (const float4*)(dist + (e0 + t) * DF);
        char* dst = smem + SH_DIST + t * 144;
#pragma unroll
        for (int j = 0; j < 16; j++) {
            float4 v = dr[j];
            uint2 h;
            h.x = packh2(v.x, v.y);
            h.y = packh2(v.z, v.w);
            *(uint2*)(dst + j * 8) = h;
        }
    }
#pragma unroll
    for (int i = 0; i < 4; i++)
        cp16(sbase + SH_W1T + (t + 256 * i) * 16, (const char*)w1T + (t + 256 * i) * 16);
    CP_COMMIT();
#pragma unroll
    for (int i = 0; i < 4; i++)
        cp16(sbase + SH_W2A + (t + 256 * i) * 16, (const char*)w2T + (t + 256 * i) * 16);
    CP_COMMIT();

    CP_WAIT(1);
    __syncthreads();

    const int lrowA = (lane & 7) + ((lane >> 3) & 1) * 8;
    const int lkA   = (lane >> 4) * 8;
    const uint32_t w1s = sbase + SH_W1T + lane * 16;

    // ---- stage 1 (per m-tile): mid fragments into mreg[mt] ----
    uint32_t mreg[2][8][4];
#pragma unroll
    for (int mt = 0; mt < 2; mt++) {
        const uint32_t aBase = sbase + SH_DIST + (wrow + mt * 16 + lrowA) * 144 + lkA * 2;
#pragma unroll
        for (int pass = 0; pass < 2; pass++) {
            float acc[8][4];
#pragma unroll
            for (int j = 0; j < 8; j++)
#pragma unroll
                for (int q = 0; q < 4; q++) acc[j][q] = 0.f;
#pragma unroll
            for (int s = 0; s < 4; s++) {
                uint32_t a[4];
                ldm_x4(a, aBase + s * 32);
#pragma unroll
                for (int p = 0; p < 4; p++) {
                    uint4 b = lds128(w1s + ((pass * 4 + p) * 4 + s) * 512);
                    mma_f16(acc[2 * p],     a, b.x, b.y);
                    mma_f16(acc[2 * p + 1], a, b.z, b.w);
                }
            }
            const float* sB1 = smF + (SH_B1 >> 2);
#pragma unroll
            for (int p = 0; p < 4; p++) {
                int nt0 = pass * 8 + 2 * p, nt1 = nt0 + 1;
                float bA0 = sB1[nt0 * 8 + 2 * c], bA1 = sB1[nt0 * 8 + 2 * c + 1];
                float bB0 = sB1[nt1 * 8 + 2 * c], bB1 = sB1[nt1 * 8 + 2 * c + 1];
                int s2i = pass * 4 + p;
                mreg[mt][s2i][0] = packh2(sspf(acc[2*p][0] + bA0),   sspf(acc[2*p][1] + bA1));
                mreg[mt][s2i][1] = packh2(sspf(acc[2*p][2] + bA0),   sspf(acc[2*p][3] + bA1));
                mreg[mt][s2i][2] = packh2(sspf(acc[2*p+1][0] + bB0), sspf(acc[2*p+1][1] + bB1));
                mreg[mt][s2i][3] = packh2(sspf(acc[2*p+1][2] + bB0), sspf(acc[2*p+1][3] + bB1));
            }
        }
    }

    // ---- 32-bit element offsets for 4 edges/thread (NOT pointers: 8 regs) ----
    int hxo[4], zo[4];
#pragma unroll
    for (int i = 0; i < 4; i++) {
        int row = wrow + (i >> 1) * 16 + (i & 1) * 8 + g;
        hxo[i] = ((int*)smem)[(SH_SEND >> 2) + row] * KER;
        zo[i]  = ((int*)smem)[(SH_RECV >> 2) + row] * (3 * KER) + zoff;
    }

    CP_WAIT(0);
    __syncthreads();

    // ---- stage 2: B fragment shared across both m-tiles ----
#pragma unroll
    for (int q = 0; q < 4; q++) {
        if (q < 3) {
            uint32_t dstq = sbase + (((q + 1) & 1) ? SH_W2B : SH_W2A);
            const char* srcq = (const char*)(w2T + (long)(q + 1) * 64 * 128);
#pragma unroll
            for (int i = 0; i < 4; i++)
                cp16(dstq + (t + 256 * i) * 16, srcq + (t + 256 * i) * 16);
            CP_COMMIT();
        }
        const uint32_t swq = sbase + ((q & 1) ? SH_W2B : SH_W2A) + lane * 16;
#pragma unroll
        for (int nb = 0; nb < 4; nb++) {
            float acc2[2][2][4];
#pragma unroll
            for (int mt = 0; mt < 2; mt++)
#pragma unroll
                for (int j = 0; j < 2; j++)
#pragma unroll
                    for (int p = 0; p < 4; p++) acc2[mt][j][p] = 0.f;
#pragma unroll
            for (int s = 0; s < 8; s++) {
                uint4 b = lds128(swq + (nb * 8 + s) * 512);
                mma_f16(acc2[0][0], mreg[0][s], b.x, b.y);
                mma_f16(acc2[0][1], mreg[0][s], b.z, b.w);
                mma_f16(acc2[1][0], mreg[1][s], b.x, b.y);
                mma_f16(acc2[1][1], mreg[1][s], b.z, b.w);
            }
            int base = q * 64 + nb * 16 + 4 * c;
#pragma unroll
            for (int mt = 0; mt < 2; mt++) {
                float4 h0 = *(const float4*)(hxsrc + hxo[2 * mt] + base);
                red4(Z + zo[2 * mt] + base,
                     acc2[mt][0][0] * h0.x, acc2[mt][0][1] * h0.y,
                     acc2[mt][1][0] * h0.z, acc2[mt][1][1] * h0.w);
                float4 h1 = *(const float4*)(hxsrc + hxo[2 * mt + 1] + base);
                red4(Z + zo[2 * mt + 1] + base,
                     acc2[mt][0][2] * h1.x, acc2[mt][0][3] * h1.y,
                     acc2[mt][1][2] * h1.z, acc2[mt][1][3] * h1.w);
            }
        }
        CP_WAIT(0);
        __syncthreads();
    }
}

// ---------------- launcher --------------------------------------------------
extern "C" void kernel_launch(void* const* d_in, const int* in_sizes, int n_in,
                              void* d_out, int out_size)
{
    const float* elec = (const float*)d_in[0];
    const float* nuc  = (const float*)d_in[1];
    const float *dist[3], *w1[3], *b1[3], *w2[3], *g[3];

    bool dictOrder = (in_sizes[3] == DF * MID);
    if (dictOrder) {
        const int base[3] = {2, 7, 12};
        for (int tI = 0; tI < 3; tI++) {
            dist[tI] = (const float*)d_in[base[tI] + 0];
            w1[tI]   = (const float*)d_in[base[tI] + 1];
            b1[tI]   = (const float*)d_in[base[tI] + 2];
            w2[tI]   = (const float*)d_in[base[tI] + 3];
            g[tI]    = (const float*)d_in[base[tI] + 4];
        }
    } else {
        for (int tI = 0; tI < 3; tI++) {
            dist[tI] = (const float*)d_in[2 + tI];
            w1[tI]   = (const float*)d_in[5 + 3 * tI];
            b1[tI]   = (const float*)d_in[6 + 3 * tI];
            w2[tI]   = (const float*)d_in[7 + 3 * tI];
            g[tI]    = (const float*)d_in[14 + tI];
        }
    }
    const float* h_w     = (const float*)d_in[17];
    const int*   send[3] = {(const int*)d_in[18], (const int*)d_in[19], (const int*)d_in[20]};
    const int*   recv[3] = {(const int*)d_in[21], (const int*)d_in[22], (const int*)d_in[23]};
    const int    E = in_sizes[2] / DF;
    const int    nblk = E / 256;

    float *HX, *Z;
    __half *Zh, *ELh, *HWh, *GTh;
    cudaGetSymbolAddress((void**)&HX,  g_HX);
    cudaGetSymbolAddress((void**)&Z,   g_Z);
    cudaGetSymbolAddress((void**)&Zh,  g_Zh);
    cudaGetSymbolAddress((void**)&ELh, g_elech);
    cudaGetSymbolAddress((void**)&HWh, g_hwh);
    cudaGetSymbolAddress((void**)&GTh, g_GTh);

    cudaFuncSetAttribute(edge_fused, cudaFuncAttributeMaxDynamicSharedMemorySize, SMEM_EDGE);
    cudaFuncSetAttribute(gemm_h, cudaFuncAttributeMaxDynamicSharedMemorySize, GSM_TOT);

    cudaMemsetAsync(Z, 0, sizeof(float) * N_ELEC * 3 * KER);

    prep_weights<<<dim3(3, 16), 256>>>(w1[0], w1[1], w1[2], w2[0], w2[1], w2[2],
                                       g[0], g[1], g[2], h_w);

    // electrons -> fp16
    {
        int n4 = N_ELEC * EMB / 4;
        f2h<<<(n4 + 255) / 256, 256>>>((const float4*)elec, (uint2*)ELh, n4);
    }
    // HX = elec @ h_w  (fp16 mma)
    {
        dim3 grid(2, N_ELEC / 64);
        gemm_h<<<grid, 256, GSM_TOT>>>(ELh, EMB, HWh, 264, nullptr, HX);
    }
    // fused fp16-mma edge kernel, 256 edges/CTA, all 3 types
    edge_fused<<<3 * nblk, 256, SMEM_EDGE>>>(dist[0], dist[1], dist[2],
                                             b1[0], b1[1], b1[2],
                                             HX, nuc,
                                             send[0], send[1], send[2],
                                             recv[0], recv[1], recv[2],
                                             Z, nblk);
    // Z -> fp16
    {
        int n4 = N_ELEC * 3 * KER / 4;
        f2h<<<(n4 + 255) / 256, 256>>>((const float4*)Z, (uint2*)Zh, n4);
    }
    // out = elec + Z @ Gcat  (fp16 mma)
    {
        dim3 grid(2, N_ELEC / 64);
        gemm_h<<<grid, 256, GSM_TOT>>>(Zh, 3 * KER, GTh, 776, elec, (float*)d_out);
    }
}

// round 14
// speedup vs baseline: 1.4066x; 1.3956x over previous
#include <cuda_runtime.h>
#include <cuda_fp16.h>
#include <math.h>
#include <stdint.h>

#define N_ELEC 8192
#define N_NUC  512
#define EMB    256
#define KER    256
#define DF     64
#define MID    128

// ---------------- scratch (device globals; no allocations allowed) ----------
__device__ __align__(16) float  g_HX[N_ELEC * KER];
__device__ __align__(16) float  g_Z[N_ELEC * 3 * KER];
// edge-kernel weight images in per-lane FRAGMENT order
__device__ __align__(16) __half g_w1Th[3][128 * 64];
__device__ __align__(16) __half g_w2Th[3][256 * 128];
// gemm_h images (n-major rows, perm16'd cols)
__device__ __align__(16) __half g_hwh[256 * 264];
__device__ __align__(16) __half g_GTh[256 * 776];

__device__ __host__ __forceinline__ int perm16(int n) {
    int c = (n >> 1) & 3, e = n & 1, ntp = (n >> 3) & 1;
    return (n & ~15) | (c << 2) | (ntp << 1) | e;
}

// ---------------- helpers ---------------------------------------------------
__device__ __forceinline__ void ldm_x4(uint32_t r[4], uint32_t saddr) {
    asm volatile("ldmatrix.sync.aligned.m8n8.x4.shared.b16 {%0,%1,%2,%3}, [%4];"
                 : "=r"(r[0]), "=r"(r[1]), "=r"(r[2]), "=r"(r[3]) : "r"(saddr));
}
__device__ __forceinline__ uint4 lds128(uint32_t saddr) {
    uint4 v;
    asm volatile("ld.shared.v4.b32 {%0,%1,%2,%3}, [%4];"
                 : "=r"(v.x), "=r"(v.y), "=r"(v.z), "=r"(v.w) : "r"(saddr));
    return v;
}
__device__ __forceinline__ void mma_f16(float acc[4], const uint32_t a[4],
                                        uint32_t b0, uint32_t b1) {
    asm volatile(
        "mma.sync.aligned.m16n8k16.row.col.f32.f16.f16.f32 "
        "{%0,%1,%2,%3}, {%4,%5,%6,%7}, {%8,%9}, {%0,%1,%2,%3};"
        : "+f"(acc[0]), "+f"(acc[1]), "+f"(acc[2]), "+f"(acc[3])
        : "r"(a[0]), "r"(a[1]), "r"(a[2]), "r"(a[3]), "r"(b0), "r"(b1));
}
__device__ __forceinline__ void red4(float* p, float x, float y, float z, float w) {
    asm volatile("red.global.add.v4.f32 [%0], {%1, %2, %3, %4};"
                 :: "l"(p), "f"(x), "f"(y), "f"(z), "f"(w) : "memory");
}
__device__ __forceinline__ void cp16(uint32_t saddr, const void* g) {
    asm volatile("cp.async.cg.shared.global [%0], [%1], 16;" :: "r"(saddr), "l"(g));
}
#define CP_COMMIT() asm volatile("cp.async.commit_group;" ::: "memory")
#define CP_WAIT(n)  asm volatile("cp.async.wait_group %0;" :: "n"(n) : "memory")

__device__ __forceinline__ uint32_t smem_u32(const void* p) {
    uint32_t a;
    asm("{ .reg .u64 t; cvta.to.shared.u64 t, %1; cvt.u32.u64 %0, t; }" : "=r"(a) : "l"(p));
    return a;
}
__device__ __forceinline__ uint32_t packh2(float x, float y) {   // lo=x, hi=y
    uint32_t r;
    asm("cvt.rn.f16x2.f32 %0, %1, %2;" : "=r"(r) : "f"(y), "f"(x));
    return r;
}
// fast shifted softplus via MUFU (validated R11)
__device__ __forceinline__ float sspf(float x) {
    float e;
    asm("ex2.approx.f32 %0, %1;" : "=f"(e) : "f"(x * 1.4426950408889634f));
    float l;
    asm("lg2.approx.f32 %0, %1;" : "=f"(l) : "f"(fmaf(e, 0.5f, 0.5f)));
    return l * 0.69314718055994531f;
}

// ================= weight prep (parallel over grid.y slices) ================
__global__ void prep_weights(const float* __restrict__ w1_0, const float* __restrict__ w1_1,
                             const float* __restrict__ w1_2,
                             const float* __restrict__ w2_0, const float* __restrict__ w2_1,
                             const float* __restrict__ w2_2,
                             const float* __restrict__ g_0, const float* __restrict__ g_1,
                             const float* __restrict__ g_2,
                             const float* __restrict__ h_w)
{
    int ty = blockIdx.x;
    const float* w1 = (ty == 0) ? w1_0 : (ty == 1) ? w1_1 : w1_2;
    const float* w2 = (ty == 0) ? w2_0 : (ty == 1) ? w2_1 : w2_2;
    const float* gg = (ty == 0) ? g_0  : (ty == 1) ? g_1  : g_2;
    const int t0 = threadIdx.x + blockIdx.y * blockDim.x;
    const int stp = blockDim.x * gridDim.y;
    for (int i = t0; i < 128 * 64; i += stp) {
        int h = i & 7, lane = (i >> 3) & 31, ks = (i >> 8) & 3, nblk = i >> 10;
        int gl = lane >> 2, cl = lane & 3, reg = h >> 1, e = h & 1;
        int k = ks * 16 + (reg & 1) * 8 + 2 * cl + e;
        int n = nblk * 16 + (reg >> 1) * 8 + gl;
        g_w1Th[ty][i] = __float2half(w1[k * 128 + n]);
    }
    for (int i = t0; i < 256 * 128; i += stp) {
        int h = i & 7, lane = (i >> 3) & 31, ks = (i >> 8) & 7, nblk = i >> 11;
        int gl = lane >> 2, cl = lane & 3, reg = h >> 1, e = h & 1;
        int k = ks * 16 + (reg & 1) * 8 + 2 * cl + e;
        int n = nblk * 16 + perm16((reg >> 1) * 8 + gl);
        g_w2Th[ty][i] = __float2half(w2[k * 256 + n]);
    }
    for (int i = t0; i < 256 * 256; i += stp) {
        int n = i >> 8, kk = i & 255;
        g_GTh[n * 776 + ty * 256 + kk] = __float2half(gg[kk * 256 + perm16(n)]);
    }
    if (ty == 0)
        for (int i = t0; i < 256 * 256; i += stp) {
            int n = i >> 8, k = i & 255;
            g_hwh[n * 264 + k] = __float2half(h_w[k * 256 + perm16(n)]);
        }
}

// ================= fp16 tensor-core GEMM, A fp32 converted on the fly =======
// Out[M,256] = (Cin?) + f16(A[M,K]) @ Bh^T.  A loaded via LDG.128 + packed to
// fp16 in-register + STS (replaces the separate f2h pass); B via cp.async.
#define GSM_A0 0
#define GSM_A1 9216
#define GSM_B0 18432
#define GSM_B1 36864
#define GSM_TOT 55296

__global__ void __launch_bounds__(256, 3)
gemm_h(const float* __restrict__ A, int K,
       const __half* __restrict__ B, int Kpad,
       const float* __restrict__ Cin, float* __restrict__ Out)
{
    extern __shared__ char smem[];
    const uint32_t sbase = smem_u32(smem);
    const int t = threadIdx.x, warp = t >> 5, lane = t & 31;
    const int wm = warp & 3, wn = warp >> 2;
    const int g = lane >> 2, c = lane & 3;
    const int n0 = blockIdx.x * 128, m0 = blockIdx.y * 64;
    const int nch = K / 64;

    const int lrowA = (lane & 7) + ((lane >> 3) & 1) * 8;
    const int lkA   = (lane >> 4) * 8;
    const int lrowB = ((lane >> 4) << 3) + (lane & 7);
    const int lkB   = ((lane >> 3) & 1) * 8;

    float acc[8][4];
#pragma unroll
    for (int j = 0; j < 8; j++)
#pragma unroll
        for (int p = 0; p < 4; p++) acc[j][p] = 0.f;

    // A: 64x64 fp32 -> fp16 smem image (stride 144B). 1024 float4 / chunk.
    // B: 128x64 fp16 via cp.async (4096B x ... = 16KB? no: 128 rows x 128B).
#define LOAD_CHUNK(ch) do {                                                     \
        uint32_t abuf = sbase + (((ch) & 1) ? GSM_A1 : GSM_A0);                 \
        uint32_t bbuf = sbase + (((ch) & 1) ? GSM_B1 : GSM_B0);                 \
        const char* bg = (const char*)(B + (long)n0 * Kpad + (ch) * 64);        \
        _Pragma("unroll")                                                       \
        for (int i = 0; i < 4; i++) {                                           \
            int idx = t + 256 * i, row = idx >> 3, cc = idx & 7;                \
            cp16(bbuf + row * 144 + cc * 16, bg + (long)row * Kpad * 2 + cc * 16); \
        }                                                                       \
        CP_COMMIT();                                                            \
        _Pragma("unroll")                                                       \
        for (int i = 0; i < 4; i++) {                                           \
            int idx = t + 256 * i, row = idx >> 4, c4 = idx & 15;               \
            float4 v = *(const float4*)(A + (long)(m0 + row) * K + (ch) * 64 + c4 * 4); \
            uint2 h;                                                            \
            h.x = packh2(v.x, v.y);                                             \
            h.y = packh2(v.z, v.w);                                             \
            *(uint2*)(smem + (abuf - sbase) + row * 144 + c4 * 8) = h;          \
        }                                                                       \
    } while (0)

    LOAD_CHUNK(0);
    for (int ch = 0; ch < nch; ch++) {
        if (ch + 1 < nch) { LOAD_CHUNK(ch + 1); CP_WAIT(1); }
        else              { CP_WAIT(0); }
        __syncthreads();
        uint32_t abuf = sbase + ((ch & 1) ? GSM_A1 : GSM_A0);
        uint32_t bbuf = sbase + ((ch & 1) ? GSM_B1 : GSM_B0);
        uint32_t aB = abuf + (wm * 16 + lrowA) * 144 + lkA * 2;
        uint32_t bB = bbuf + (wn * 64 + lrowB) * 144 + lkB * 2;
#pragma unroll
        for (int s = 0; s < 4; s++) {
            uint32_t a[4];
            ldm_x4(a, aB + s * 32);
#pragma unroll
            for (int p = 0; p < 4; p++) {
                uint32_t b[4];
                ldm_x4(b, bB + p * 16 * 144 + s * 32);
                mma_f16(acc[2 * p],     a, b[0], b[1]);
                mma_f16(acc[2 * p + 1], a, b[2], b[3]);
            }
        }
        __syncthreads();
    }

    int ra = m0 + wm * 16 + g, rb = ra + 8;
#pragma unroll
    for (int p = 0; p < 4; p++) {
        int col = n0 + wn * 64 + p * 16 + 4 * c;
        float4 v0 = make_float4(acc[2*p][0], acc[2*p][1], acc[2*p+1][0], acc[2*p+1][1]);
        float4 v1 = make_float4(acc[2*p][2], acc[2*p][3], acc[2*p+1][2], acc[2*p+1][3]);
        if (Cin) {
            float4 c0 = *(const float4*)(Cin + (long)ra * 256 + col);
            float4 c1 = *(const float4*)(Cin + (long)rb * 256 + col);
            v0.x += c0.x; v0.y += c0.y; v0.z += c0.z; v0.w += c0.w;
            v1.x += c1.x; v1.y += c1.y; v1.z += c1.z; v1.w += c1.w;
        }
        *(float4*)(Out + (long)ra * 256 + col) = v0;
        *(float4*)(Out + (long)rb * 256 + col) = v1;
    }
}

// ================= fused fp16 mma edge kernel (R11, validated 179us) ========
#define SH_B1    0
#define SH_SEND  512
#define SH_RECV  1024
#define SH_DIST  1536
#define SH_W1T   19968
#define SH_W2A   36352
#define SH_W2B   52736
#define SMEM_EDGE 69120

__global__ void __launch_bounds__(256, 3)
edge_fused(const float* __restrict__ dist0, const float* __restrict__ dist1,
           const float* __restrict__ dist2,
           const float* __restrict__ b1_0, const float* __restrict__ b1_1,
           const float* __restrict__ b1_2,
           const float* __restrict__ HX, const float* __restrict__ nuc,
           const int* __restrict__ s0, const int* __restrict__ s1, const int* __restrict__ s2,
           const int* __restrict__ r0p, const int* __restrict__ r1p, const int* __restrict__ r2p,
           float* __restrict__ Z, int nblk)
{
    extern __shared__ char smem[];
    float* smF = (float*)smem;
    const uint32_t sbase = smem_u32(smem);
    const int t = threadIdx.x, warp = t >> 5, lane = t & 31;
    const int g = lane >> 2, c = lane & 3;
    const int wr0 = warp * 16;

    const int ty  = blockIdx.x / nblk;
    const int blk = blockIdx.x - ty * nblk;
    const float* dist  = (ty == 0) ? dist0 : (ty == 1) ? dist1 : dist2;
    const float* b1    = (ty == 0) ? b1_0  : (ty == 1) ? b1_1  : b1_2;
    const int*   snd   = (ty == 0) ? s0 : (ty == 1) ? s1 : s2;
    const int*   rcv   = (ty == 0) ? r0p : (ty == 1) ? r1p : r2p;
    const float* hxsrc = (ty == 2) ? nuc : HX;
    const int    zoff  = ty * KER;
    const long   e0    = (long)blk * 128;
    const __half* w1T  = g_w1Th[ty];
    const __half* w2T  = g_w2Th[ty];

    // ---- fill ----
    if (t < 128) {
        smF[(SH_B1 >> 2) + t] = b1[t];
        ((int*)smem)[(SH_SEND >> 2) + t] = snd[e0 + t];
        ((int*)smem)[(SH_RECV >> 2) + t] = rcv[e0 + t];
    }
    {
        int row = t >> 1, part = t & 1;
        const float4* dr = (const float4*)(dist + (e0 + row) * DF);
        char* dst = smem + SH_DIST + row * 144;
#pragma unroll
        for (int j = 0; j < 8; j++) {
            int c4 = part * 8 + j;
            float4 v = dr[c4];
            uint2 h;
            h.x = packh2(v.x, v.y);
            h.y = packh2(v.z, v.w);
            *(uint2*)(dst + c4 * 8) = h;
        }
    }
#pragma unroll
    for (int i = 0; i < 4; i++)
        cp16(sbase + SH_W1T + (t + 256 * i) * 16, (const char*)w1T + (t + 256 * i) * 16);
    CP_COMMIT();
#pragma unroll
    for (int i = 0; i < 4; i++)
        cp16(sbase + SH_W2A + (t + 256 * i) * 16, (const char*)w2T + (t + 256 * i) * 16);
    CP_COMMIT();

    CP_WAIT(1);
    __syncthreads();

    const int lrowA = (lane & 7) + ((lane >> 3) & 1) * 8;
    const int lkA   = (lane >> 4) * 8;
    const uint32_t aBase = sbase + SH_DIST + (wr0 + lrowA) * 144 + lkA * 2;
    const uint32_t w1s   = sbase + SH_W1T + lane * 16;

    // ---- stage 1 ----
    uint32_t mreg[8][4];
#pragma unroll
    for (int pass = 0; pass < 2; pass++) {
        float acc[8][4];
#pragma unroll
        for (int j = 0; j < 8; j++)
#pragma unroll
            for (int q = 0; q < 4; q++) acc[j][q] = 0.f;
#pragma unroll
        for (int s = 0; s < 4; s++) {
            uint32_t a[4];
            ldm_x4(a, aBase + s * 32);
#pragma unroll
            for (int p = 0; p < 4; p++) {
                uint4 b = lds128(w1s + ((pass * 4 + p) * 4 + s) * 512);
                mma_f16(acc[2 * p],     a, b.x, b.y);
                mma_f16(acc[2 * p + 1], a, b.z, b.w);
            }
        }
        const float* sB1 = smF + (SH_B1 >> 2);
#pragma unroll
        for (int p = 0; p < 4; p++) {
            int nt0 = pass * 8 + 2 * p, nt1 = nt0 + 1;
            float bA0 = sB1[nt0 * 8 + 2 * c], bA1 = sB1[nt0 * 8 + 2 * c + 1];
            float bB0 = sB1[nt1 * 8 + 2 * c], bB1 = sB1[nt1 * 8 + 2 * c + 1];
            int s2i = pass * 4 + p;
            mreg[s2i][0] = packh2(sspf(acc[2*p][0] + bA0),   sspf(acc[2*p][1] + bA1));
            mreg[s2i][1] = packh2(sspf(acc[2*p][2] + bA0),   sspf(acc[2*p][3] + bA1));
            mreg[s2i][2] = packh2(sspf(acc[2*p+1][0] + bB0), sspf(acc[2*p+1][1] + bB1));
            mreg[s2i][3] = packh2(sspf(acc[2*p+1][2] + bB0), sspf(acc[2*p+1][3] + bB1));
        }
    }

    const int ra = wr0 + g, rb = wr0 + g + 8;
    const int sa = ((int*)smem)[(SH_SEND >> 2) + ra];
    const int sb = ((int*)smem)[(SH_SEND >> 2) + rb];
    const int qa = ((int*)smem)[(SH_RECV >> 2) + ra];
    const int qb = ((int*)smem)[(SH_RECV >> 2) + rb];
    const float* hxa = hxsrc + (long)sa * KER;
    const float* hxb = hxsrc + (long)sb * KER;
    float* Za = Z + (long)qa * (3 * KER) + zoff;
    float* Zb = Z + (long)qb * (3 * KER) + zoff;

    CP_WAIT(0);
    __syncthreads();

    // ---- stage 2 ----
#pragma unroll
    for (int q = 0; q < 4; q++) {
        if (q < 3) {
            uint32_t dstq = sbase + (((q + 1) & 1) ? SH_W2B : SH_W2A);
            const char* srcq = (const char*)(w2T + (long)(q + 1) * 64 * 128);
#pragma unroll
            for (int i = 0; i < 4; i++)
                cp16(dstq + (t + 256 * i) * 16, srcq + (t + 256 * i) * 16);
            CP_COMMIT();
        }
        const uint32_t swq = sbase + ((q & 1) ? SH_W2B : SH_W2A) + lane * 16;
#pragma unroll
        for (int nb = 0; nb < 4; nb++) {
            float acc2[2][4];
#pragma unroll
            for (int j = 0; j < 2; j++)
#pragma unroll
                for (int p = 0; p < 4; p++) acc2[j][p] = 0.f;
#pragma unroll
            for (int s = 0; s < 8; s++) {
                uint4 b = lds128(swq + (nb * 8 + s) * 512);
                mma_f16(acc2[0], mreg[s], b.x, b.y);
                mma_f16(acc2[1], mreg[s], b.z, b.w);
            }
            int base = q * 64 + nb * 16 + 4 * c;
            float4 ha = *(const float4*)(hxa + base);
            red4(Za + base, acc2[0][0] * ha.x, acc2[0][1] * ha.y,
                            acc2[1][0] * ha.z, acc2[1][1] * ha.w);
            float4 hb = *(const float4*)(hxb + base);
            red4(Zb + base, acc2[0][2] * hb.x, acc2[0][3] * hb.y,
                            acc2[1][2] * hb.z, acc2[1][3] * hb.w);
        }
        CP_WAIT(0);
        __syncthreads();
    }
}

// ---------------- launcher --------------------------------------------------
extern "C" void kernel_launch(void* const* d_in, const int* in_sizes, int n_in,
                              void* d_out, int out_size)
{
    const float* elec = (const float*)d_in[0];
    const float* nuc  = (const float*)d_in[1];
    const float *dist[3], *w1[3], *b1[3], *w2[3], *g[3];

    bool dictOrder = (in_sizes[3] == DF * MID);
    if (dictOrder) {
        const int base[3] = {2, 7, 12};
        for (int tI = 0; tI < 3; tI++) {
            dist[tI] = (const float*)d_in[base[tI] + 0];
            w1[tI]   = (const float*)d_in[base[tI] + 1];
            b1[tI]   = (const float*)d_in[base[tI] + 2];
            w2[tI]   = (const float*)d_in[base[tI] + 3];
            g[tI]    = (const float*)d_in[base[tI] + 4];
        }
    } else {
        for (int tI = 0; tI < 3; tI++) {
            dist[tI] = (const float*)d_in[2 + tI];
            w1[tI]   = (const float*)d_in[5 + 3 * tI];
            b1[tI]   = (const float*)d_in[6 + 3 * tI];
            w2[tI]   = (const float*)d_in[7 + 3 * tI];
            g[tI]    = (const float*)d_in[14 + tI];
        }
    }
    const float* h_w     = (const float*)d_in[17];
    const int*   send[3] = {(const int*)d_in[18], (const int*)d_in[19], (const int*)d_in[20]};
    const int*   recv[3] = {(const int*)d_in[21], (const int*)d_in[22], (const int*)d_in[23]};
    const int    E = in_sizes[2] / DF;
    const int    nblk = E / 128;

    float *HX, *Z;
    __half *HWh, *GTh;
    cudaGetSymbolAddress((void**)&HX,  g_HX);
    cudaGetSymbolAddress((void**)&Z,   g_Z);
    cudaGetSymbolAddress((void**)&HWh, g_hwh);
    cudaGetSymbolAddress((void**)&GTh, g_GTh);

    cudaFuncSetAttribute(edge_fused, cudaFuncAttributeMaxDynamicSharedMemorySize, SMEM_EDGE);
    cudaFuncSetAttribute(gemm_h, cudaFuncAttributeMaxDynamicSharedMemorySize, GSM_TOT);

    cudaMemsetAsync(Z, 0, sizeof(float) * N_ELEC * 3 * KER);

    prep_weights<<<dim3(3, 16), 256>>>(w1[0], w1[1], w1[2], w2[0], w2[1], w2[2],
                                       g[0], g[1], g[2], h_w);

    // HX = f16(elec) @ h_w  (conversion fused into A-loader)
    {
        dim3 grid(2, N_ELEC / 64);
        gemm_h<<<grid, 256, GSM_TOT>>>(elec, EMB, HWh, 264, nullptr, HX);
    }
    // fused fp16-mma edge kernel, 128 edges/CTA (validated R11), all 3 types
    edge_fused<<<3 * nblk, 256, SMEM_EDGE>>>(dist[0], dist[1], dist[2],
                                             b1[0], b1[1], b1[2],
                                             HX, nuc,
                                             send[0], send[1], send[2],
                                             recv[0], recv[1], recv[2],
                                             Z, nblk);
    // out = elec + f16(Z) @ Gcat  (conversion fused into A-loader)
    {
        dim3 grid(2, N_ELEC / 64);
        gemm_h<<<grid, 256, GSM_TOT>>>(Z, 3 * KER, GTh, 776, elec, (float*)d_out);
    }
}